// round 14
// baseline (speedup 1.0000x reference)
#include <cuda_runtime.h>
#include <cuda_fp16.h>
#include <cstdint>

// ---------------------------------------------------------------------------
#define BATCH   16384
#define D_IN    256
#define D_H     512
#define NQ      12
#define NLAYERS 4
#define FULLM   0xffffffffu

typedef unsigned long long ull;

// Scratch buffers
__device__ float  g_h[(size_t)BATCH * D_H];            // 32 MB  fp32 h
__device__ float2 g_cs[(size_t)BATCH * NQ];            // 1.5 MB (cos,sin) per sample/wire

__host__ __device__ constexpr int cpop(int v) {
    int c = 0;
    for (int i = 0; i < 12; i++) c += (v >> i) & 1;
    return c;
}
__host__ __device__ constexpr int e5(int r) {            // 5-bit suffix-xor
    return (r ^ (r >> 1) ^ (r >> 2) ^ (r >> 3) ^ (r >> 4)) & 31;
}
__host__ __device__ constexpr int gray5(int r) { return (r ^ (r >> 1)) & 31; }

// ---- packed f32x2 helpers (sm_100a) ----
__device__ __forceinline__ ull pk2(float x, float y) {
    ull r; asm("mov.b64 %0, {%1,%2};" : "=l"(r) : "f"(x), "f"(y)); return r;
}
__device__ __forceinline__ ull pkb(float x) { return pk2(x, x); }
__device__ __forceinline__ void upk(ull v, float& x, float& y) {
    asm("mov.b64 {%0,%1}, %2;" : "=f"(x), "=f"(y) : "l"(v));
}
__device__ __forceinline__ ull fma2(ull a, ull b, ull c) {
    ull d; asm("fma.rn.f32x2 %0, %1, %2, %3;" : "=l"(d) : "l"(a), "l"(b), "l"(c)); return d;
}
__device__ __forceinline__ ull mul2(ull a, ull b) {
    ull d; asm("mul.rn.f32x2 %0, %1, %2;" : "=l"(d) : "l"(a), "l"(b)); return d;
}
__device__ __forceinline__ ull add2(ull a, ull b) {
    ull d; asm("add.rn.f32x2 %0, %1, %2;" : "=l"(d) : "l"(a), "l"(b)); return d;
}
// fp16x2 <-> f32x2 conversion
__device__ __forceinline__ uint32_t pkh(ull v) {
    float x, y; upk(v, x, y);
    __half2 h = __floats2half2_rn(x, y);
    return *reinterpret_cast<uint32_t*>(&h);
}
__device__ __forceinline__ ull uph(uint32_t u) {
    __half2 h = *reinterpret_cast<__half2*>(&u);
    float2 f = __half22float2(h);
    return pk2(f.x, f.y);
}
// packed fp16x2 math
__device__ __forceinline__ uint32_t hfma2u(uint32_t a, uint32_t b, uint32_t c) {
    uint32_t d;
    asm("fma.rn.f16x2 %0, %1, %2, %3;" : "=r"(d) : "r"(a), "r"(b), "r"(c));
    return d;
}
__device__ __forceinline__ uint32_t pkh2f(float x) {
    __half2 h = __float2half2_rn(x);
    return *reinterpret_cast<uint32_t*>(&h);
}
// 8x fp32 -> 8x fp16 packed in int4
__device__ __forceinline__ int4 cvt8h(float4 a, float4 b) {
    __half2 h0 = __floats2half2_rn(a.x, a.y);
    __half2 h1 = __floats2half2_rn(a.z, a.w);
    __half2 h2 = __floats2half2_rn(b.x, b.y);
    __half2 h3 = __floats2half2_rn(b.z, b.w);
    int4 r;
    r.x = *reinterpret_cast<int*>(&h0);
    r.y = *reinterpret_cast<int*>(&h1);
    r.z = *reinterpret_cast<int*>(&h2);
    r.w = *reinterpret_cast<int*>(&h3);
    return r;
}

// ---- tensor-core helpers ----
__device__ __forceinline__ void ldsm_x4(uint32_t& r0, uint32_t& r1,
                                        uint32_t& r2, uint32_t& r3, uint32_t addr) {
    asm volatile("ldmatrix.sync.aligned.m8n8.x4.shared.b16 {%0,%1,%2,%3}, [%4];"
                 : "=r"(r0), "=r"(r1), "=r"(r2), "=r"(r3) : "r"(addr));
}
__device__ __forceinline__ void ldsm_x4_t(uint32_t& r0, uint32_t& r1,
                                          uint32_t& r2, uint32_t& r3, uint32_t addr) {
    asm volatile("ldmatrix.sync.aligned.m8n8.x4.trans.shared.b16 {%0,%1,%2,%3}, [%4];"
                 : "=r"(r0), "=r"(r1), "=r"(r2), "=r"(r3) : "r"(addr));
}
__device__ __forceinline__ void mma16816(float* c, const uint32_t* a, const uint32_t* b) {
    asm volatile("mma.sync.aligned.m16n8k16.row.col.f32.f16.f16.f32 "
                 "{%0,%1,%2,%3}, {%4,%5,%6,%7}, {%8,%9}, {%0,%1,%2,%3};"
                 : "+f"(c[0]), "+f"(c[1]), "+f"(c[2]), "+f"(c[3])
                 : "r"(a[0]), "r"(a[1]), "r"(a[2]), "r"(a[3]), "r"(b[0]), "r"(b[1]));
}

// ---------------------------------------------------------------------------
// Kernel 1: h = relu(data @ W_graph + bias), HMMA 16816, fp32 accumulate.
// fp32 inputs converted to fp16 in registers (cvt kernel fused away).
// ---------------------------------------------------------------------------
__global__ void __launch_bounds__(256)
hgemm_relu_kernel(const float* __restrict__ Af,   // [BATCH, D_IN] fp32
                  const float* __restrict__ Bf,   // [D_IN, D_H]  fp32
                  const float* __restrict__ bias)
{
    __shared__ __half As[128][40];
    __shared__ __half Bs[32][136];

    const int tid  = threadIdx.x;
    const int wid  = tid >> 5;
    const int lane = tid & 31;
    const int rowBase = blockIdx.y * 128;
    const int colBase = blockIdx.x * 128;
    const int wm = (wid >> 2) * 64;
    const int wn = (wid & 3) * 32;

    float acc[4][4][4];
#pragma unroll
    for (int mb = 0; mb < 4; mb++)
#pragma unroll
        for (int nb = 0; nb < 4; nb++)
#pragma unroll
            for (int k = 0; k < 4; k++) acc[mb][nb][k] = 0.f;

    const int aIdx0 = tid * 2;
    const int aRow0 = aIdx0 >> 2, aChk0 = (aIdx0 & 3);
    const int aRow1 = (aIdx0 + 1) >> 2, aChk1 = ((aIdx0 + 1) & 3);
    const int bRow0 = aIdx0 >> 4, bChk0 = (aIdx0 & 15);
    const int bRow1 = (aIdx0 + 1) >> 4, bChk1 = ((aIdx0 + 1) & 15);

    const float* Ag = Af + (size_t)rowBase * D_IN;

    const int g = lane >> 3, li = lane & 7;
    const uint32_t AsBase = (uint32_t)__cvta_generic_to_shared(&As[0][0]);
    const uint32_t BsBase = (uint32_t)__cvta_generic_to_shared(&Bs[0][0]);
    const uint32_t addrA0 = AsBase + (uint32_t)((wm + (g & 1) * 8 + li) * 80 + (g >> 1) * 16);
    const uint32_t addrB0 = BsBase + (uint32_t)(((g & 1) * 8 + li) * 272 + (wn + (g >> 1) * 8) * 2);

    float4 fa0a, fa0b, fa1a, fa1b, fb0a, fb0b, fb1a, fb1b;
    {
        const float* p;
        p = Ag + (size_t)aRow0 * D_IN + aChk0 * 8;
        fa0a = *reinterpret_cast<const float4*>(p);
        fa0b = *reinterpret_cast<const float4*>(p + 4);
        p = Ag + (size_t)aRow1 * D_IN + aChk1 * 8;
        fa1a = *reinterpret_cast<const float4*>(p);
        fa1b = *reinterpret_cast<const float4*>(p + 4);
        p = Bf + (size_t)bRow0 * D_H + colBase + bChk0 * 8;
        fb0a = *reinterpret_cast<const float4*>(p);
        fb0b = *reinterpret_cast<const float4*>(p + 4);
        p = Bf + (size_t)bRow1 * D_H + colBase + bChk1 * 8;
        fb1a = *reinterpret_cast<const float4*>(p);
        fb1b = *reinterpret_cast<const float4*>(p + 4);
    }

    for (int kc = 0; kc < 8; kc++) {
        *reinterpret_cast<int4*>(&As[aRow0][aChk0 * 8]) = cvt8h(fa0a, fa0b);
        *reinterpret_cast<int4*>(&As[aRow1][aChk1 * 8]) = cvt8h(fa1a, fa1b);
        *reinterpret_cast<int4*>(&Bs[bRow0][bChk0 * 8]) = cvt8h(fb0a, fb0b);
        *reinterpret_cast<int4*>(&Bs[bRow1][bChk1 * 8]) = cvt8h(fb1a, fb1b);
        __syncthreads();

        if (kc < 7) {
            const int k0n = (kc + 1) * 32;
            const float* p;
            p = Ag + (size_t)aRow0 * D_IN + k0n + aChk0 * 8;
            fa0a = *reinterpret_cast<const float4*>(p);
            fa0b = *reinterpret_cast<const float4*>(p + 4);
            p = Ag + (size_t)aRow1 * D_IN + k0n + aChk1 * 8;
            fa1a = *reinterpret_cast<const float4*>(p);
            fa1b = *reinterpret_cast<const float4*>(p + 4);
            p = Bf + (size_t)(k0n + bRow0) * D_H + colBase + bChk0 * 8;
            fb0a = *reinterpret_cast<const float4*>(p);
            fb0b = *reinterpret_cast<const float4*>(p + 4);
            p = Bf + (size_t)(k0n + bRow1) * D_H + colBase + bChk1 * 8;
            fb1a = *reinterpret_cast<const float4*>(p);
            fb1b = *reinterpret_cast<const float4*>(p + 4);
        }

#pragma unroll
        for (int k16 = 0; k16 < 2; k16++) {
            uint32_t a[4][4];
#pragma unroll
            for (int mb = 0; mb < 4; mb++)
                ldsm_x4(a[mb][0], a[mb][1], a[mb][2], a[mb][3],
                        addrA0 + (uint32_t)(mb * 16 * 80 + k16 * 32));
            uint32_t b[4][2];
#pragma unroll
            for (int nb2 = 0; nb2 < 2; nb2++) {
                uint32_t r0, r1, r2, r3;
                ldsm_x4_t(r0, r1, r2, r3,
                          addrB0 + (uint32_t)(nb2 * 32 + k16 * 16 * 272));
                b[nb2 * 2 + 0][0] = r0; b[nb2 * 2 + 0][1] = r1;
                b[nb2 * 2 + 1][0] = r2; b[nb2 * 2 + 1][1] = r3;
            }
#pragma unroll
            for (int mb = 0; mb < 4; mb++)
#pragma unroll
                for (int nb = 0; nb < 4; nb++)
                    mma16816(acc[mb][nb], a[mb], b[nb]);
        }
        __syncthreads();
    }

#pragma unroll
    for (int nb = 0; nb < 4; nb++) {
        const int col = colBase + wn + nb * 8 + (lane & 3) * 2;
        const float2 bz = *reinterpret_cast<const float2*>(&bias[col]);
#pragma unroll
        for (int mb = 0; mb < 4; mb++) {
            const int row0 = rowBase + wm + mb * 16 + (lane >> 2);
            float2 v0, v1;
            v0.x = fmaxf(acc[mb][nb][0] + bz.x, 0.f);
            v0.y = fmaxf(acc[mb][nb][1] + bz.y, 0.f);
            v1.x = fmaxf(acc[mb][nb][2] + bz.x, 0.f);
            v1.y = fmaxf(acc[mb][nb][3] + bz.y, 0.f);
            *reinterpret_cast<float2*>(&g_h[(size_t)row0 * D_H + col]) = v0;
            *reinterpret_cast<float2*>(&g_h[(size_t)(row0 + 8) * D_H + col]) = v1;
        }
    }
}

// ---------------------------------------------------------------------------
// Kernel 1.5: pre_kernel — x = h @ W_pre + b_pre -> angles -> g_cs.
// (unchanged)
// ---------------------------------------------------------------------------
__global__ void __launch_bounds__(256)
pre_kernel(const float* __restrict__ Wp,   // [D_H, NQ] row-major
           const float* __restrict__ bp,   // [NQ]
           const float* __restrict__ qw)   // [NLAYERS*NQ]
{
    __shared__ float WpS[NQ][D_H];         // 24 KB transposed copy

    const int tid  = threadIdx.x;
    const int wid  = tid >> 5;
    const int lane = tid & 31;

    for (int e = tid; e < NQ * D_H; e += 256) {
        const int q = e >> 9;
        const int k = e & 511;
        WpS[q][k] = Wp[k * NQ + q];
    }
    __syncthreads();

    const int s = blockIdx.x * 8 + wid;
    const float* hr = g_h + (size_t)s * D_H;

    ull xa2[NQ];
#pragma unroll
    for (int q = 0; q < NQ; q++) xa2[q] = 0ull;

#pragma unroll
    for (int j = 0; j < 8; j++) {
        const int k0 = j * 64 + lane * 2;
        const ull hv2 = *reinterpret_cast<const ull*>(hr + k0);
#pragma unroll
        for (int q = 0; q < NQ; q++) {
            const ull wq2 = *reinterpret_cast<const ull*>(&WpS[q][k0]);
            xa2[q] = fma2(hv2, wq2, xa2[q]);
        }
    }

    float myx = 0.f;
#pragma unroll
    for (int q = 0; q < NQ; q++) {
        float a, b;
        upk(xa2[q], a, b);
        float v = a + b;
#pragma unroll
        for (int o = 16; o; o >>= 1) v += __shfl_xor_sync(FULLM, v, o);
        if (lane == q) myx = v;
    }

    if (lane < NQ) {
        const float x = myx + bp[lane];
        const float half = fmaf(0.5f, atanf(x), 0.78539816339744831f)
                         + 0.5f * qw[lane];
        float sv, cv;
        sincosf(half, &sv, &cv);
        g_cs[(size_t)s * NQ + lane] = make_float2(cv, sv);
    }
}

// ---------------------------------------------------------------------------
// Kernel 2: 12-qubit sim -> expectation. 2 samples per block.
// All-fp16 layer loop (R12); launch_bounds(128,8) -> 64-reg target, 8 blk/SM.
// ---------------------------------------------------------------------------
__global__ void __launch_bounds__(128, 8)
sim_kernel(const float* __restrict__ qw,   // [NLAYERS*NQ]
           float* __restrict__ out)        // [BATCH]
{
    extern __shared__ uint32_t SH[];       // 4096 fp16x2 amplitudes (16 KB)
    __shared__ uint32_t qh[NLAYERS * NQ];  // {t, t}  packed fp16x2
    __shared__ uint32_t qhn[NLAYERS * NQ]; // {-t,-t} packed fp16x2
    __shared__ float cS[2][NQ], sS[2][NQ];
    __shared__ float2 redc[4];
    __shared__ float CfS;

    const int tid  = threadIdx.x;
    const int w    = tid >> 5;      // 0..3
    const int lane = tid & 31;
    const int s0   = blockIdx.x * 2;

    if (tid < NLAYERS * NQ) {
        float a = qw[tid] * 0.5f;
        float sv, cv;
        sincosf(a, &sv, &cv);
        const float t = sv / cv;
        qh[tid]  = pkh2f(t);
        qhn[tid] = pkh2f(-t);
    }
    if (tid == 64) {
        float C = 1.f;
        for (int i = NQ; i < NLAYERS * NQ; i++) C *= cosf(qw[i] * 0.5f);
        CfS = C;
    }
    if (tid >= 96 && tid < 96 + 2 * NQ) {
        const int e = tid - 96;
        const int smp = e / NQ, q = e % NQ;
        const float2 v = g_cs[(size_t)(s0 + smp) * NQ + q];
        cS[smp][q] = v.x;
        sS[smp][q] = v.y;
    }
    __syncthreads();

    // ---- initial product state, layout A, fp32 (merged layer-1 RYs) ----
    float bx = CfS, by = CfS;
#pragma unroll
    for (int b = 0; b < 5; b++) {
        const int wr = 11 - b;
        if ((lane >> b) & 1) { bx *= sS[0][wr]; by *= sS[1][wr]; }
        else                 { bx *= cS[0][wr]; by *= cS[1][wr]; }
    }
    if (w & 1)  { bx *= sS[0][6]; by *= sS[1][6]; }
    else        { bx *= cS[0][6]; by *= cS[1][6]; }
    if (w >> 1) { bx *= sS[0][5]; by *= sS[1][5]; }
    else        { bx *= cS[0][5]; by *= cS[1][5]; }

    ull st[32];
    st[0] = pk2(bx, by);
#pragma unroll
    for (int tb = 0; tb < 5; tb++) {
        const int wirew = 4 - tb;
        const ull cp = pk2(cS[0][wirew], cS[1][wirew]);
        const ull sp = pk2(sS[0][wirew], sS[1][wirew]);
#pragma unroll
        for (int r = 0; r < (1 << tb); r++) {
            st[r | (1 << tb)] = mul2(st[r], sp);
            st[r] = mul2(st[r], cp);
        }
    }

    // one-time pack to fp16x2
    uint32_t sh[32];
#pragma unroll
    for (int r = 0; r < 32; r++) sh[r] = pkh(st[r]);

    // ---- storage-map bases:  sigma(q) = q ^ e5(q[9:5]) ----
    const int e5w = e5(w);
    const int base2 = (w << 10) | (lane << 5);
    const int e5l = e5(lane);
    int RB1;
    {
        const int g0 = base2 ^ (base2 >> 1);
        RB1 = g0 ^ e5((g0 >> 5) & 31);
    }
    const int tAlo = (w << 5) | (lane ^ e5w);

    // ---- 3 remaining layers, all-fp16 pipeline ----
#pragma unroll 1
    for (int ell = 0; ell < 3; ell++) {
        const int qb = NQ * (ell + 1);

        // trip: A -> B composed with gray perm
        __syncthreads();
#pragma unroll
        for (int r = 0; r < 32; r++)
            SH[(r << 7) | (tAlo ^ e5((r & 7) << 2))] = sh[r];
        __syncthreads();
#pragma unroll
        for (int r = 0; r < 32; r++)
            sh[r] = SH[RB1 ^ gray5(r)];

        // wires 7..11 on layout-B reg bits (bt = 11-u), fp16x2
#pragma unroll
        for (int u = 7; u < 12; u++) {
            const uint32_t tp = qh[qb + u];
            const uint32_t np = qhn[qb + u];
            const int bt = 11 - u;
#pragma unroll
            for (int r = 0; r < 32; r++) {
                if (((r >> bt) & 1) == 0) {
                    const int j = r | (1 << bt);
                    const uint32_t A = sh[r], B = sh[j];
                    sh[r] = hfma2u(np, B, A);
                    sh[j] = hfma2u(tp, A, B);
                }
            }
        }

        // wire 6 (lane bit 0) and wire 5 (lane bit 1): 32-bit shfl + hfma2
        {
            const uint32_t sg6 = (lane & 1) ? qh[qb + 6] : qhn[qb + 6];
#pragma unroll
            for (int r = 0; r < 32; r++) {
                const uint32_t p = __shfl_xor_sync(FULLM, sh[r], 1);
                sh[r] = hfma2u(sg6, p, sh[r]);
            }
            const uint32_t sg5 = ((lane >> 1) & 1) ? qh[qb + 5] : qhn[qb + 5];
#pragma unroll
            for (int r = 0; r < 32; r++) {
                const uint32_t p = __shfl_xor_sync(FULLM, sh[r], 2);
                sh[r] = hfma2u(sg5, p, sh[r]);
            }
        }

        // trip: B -> A
        __syncthreads();
#pragma unroll
        for (int r = 0; r < 32; r++)
            SH[base2 | (r ^ e5l)] = sh[r];
        __syncthreads();
#pragma unroll
        for (int r = 0; r < 32; r++)
            sh[r] = SH[(r << 7) | (tAlo ^ e5((r & 7) << 2))];

        // wires 0..4 on layout-A reg bits (bt = 4-u), fp16x2
#pragma unroll
        for (int u = 0; u < 5; u++) {
            const uint32_t tp = qh[qb + u];
            const uint32_t np = qhn[qb + u];
            const int bt = 4 - u;
#pragma unroll
            for (int r = 0; r < 32; r++) {
                if (((r >> bt) & 1) == 0) {
                    const int j = r | (1 << bt);
                    const uint32_t A = sh[r], B = sh[j];
                    sh[r] = hfma2u(np, B, A);
                    sh[j] = hfma2u(tp, A, B);
                }
            }
        }
    }

    // ---- measurement (fp32) with final gray perm folded into weights ----
    int ex = tid;
    ex ^= ex >> 1; ex ^= ex >> 2; ex ^= ex >> 4;
    const int Pt = __popc(ex & 127);

    ull acc1 = 0ull, accP = 0ull, accM = 0ull;
#pragma unroll
    for (int r = 0; r < 32; r++) {
        const int a = cpop(e5(r));
        const int p = cpop(r) & 1;
        const float Ar = p ? (float)(-2 - 2 * a) : (float)(12 - 2 * a);
        const ull v = uph(sh[r]);
        const ull t = mul2(v, v);
        acc1 = fma2(pkb(Ar), t, acc1);
        if (p) accP = add2(accP, t);
        else   accM = add2(accM, t);
    }
    const ull S = fma2(pkb(-1.f), accM, accP);
    const ull res = fma2(pkb(2.f * (float)Pt), S, acc1);

    float rx, ry;
    upk(res, rx, ry);
#pragma unroll
    for (int o = 16; o; o >>= 1) {
        rx += __shfl_xor_sync(FULLM, rx, o);
        ry += __shfl_xor_sync(FULLM, ry, o);
    }
    if (lane == 0) redc[w] = make_float2(rx, ry);
    __syncthreads();
    if (tid == 0) {
        out[s0]     = redc[0].x + redc[1].x + redc[2].x + redc[3].x;
        out[s0 + 1] = redc[0].y + redc[1].y + redc[2].y + redc[3].y;
    }
}

// ---------------------------------------------------------------------------
extern "C" void kernel_launch(void* const* d_in, const int* in_sizes, int n_in,
                              void* d_out, int out_size)
{
    const float* data = (const float*)d_in[0];
    const float* Wg   = (const float*)d_in[1];
    const float* bg   = (const float*)d_in[2];
    const float* Wp   = (const float*)d_in[3];
    const float* bp   = (const float*)d_in[4];
    const float* qw   = (const float*)d_in[5];
    float* out = (float*)d_out;

    dim3 gGrid(D_H / 128, BATCH / 128);
    hgemm_relu_kernel<<<gGrid, 256>>>(data, Wg, bg);

    pre_kernel<<<BATCH / 8, 256>>>(Wp, bp, qw);

    sim_kernel<<<BATCH / 2, 128, 16384>>>(qw, out);
}

// round 17
// speedup vs baseline: 1.0866x; 1.0866x over previous
#include <cuda_runtime.h>
#include <cuda_fp16.h>
#include <cstdint>

// ---------------------------------------------------------------------------
#define BATCH   16384
#define D_IN    256
#define D_H     512
#define NQ      12
#define NLAYERS 4
#define FULLM   0xffffffffu

typedef unsigned long long ull;

// Scratch buffers
__device__ __half g_h16[(size_t)BATCH * D_H];          // 16 MB  fp16 h
__device__ __half g_Ah[(size_t)BATCH * D_IN];          // 8 MB   fp16 data
__device__ __half g_Bh[(size_t)D_IN * D_H];            // 256 KB fp16 W_graph
__device__ float2 g_cs[(size_t)BATCH * NQ];            // 1.5 MB (cos,sin) per sample/wire

__host__ __device__ constexpr int cpop(int v) {
    int c = 0;
    for (int i = 0; i < 12; i++) c += (v >> i) & 1;
    return c;
}
__host__ __device__ constexpr int e5(int r) {            // 5-bit suffix-xor
    return (r ^ (r >> 1) ^ (r >> 2) ^ (r >> 3) ^ (r >> 4)) & 31;
}
__host__ __device__ constexpr int gray5(int r) { return (r ^ (r >> 1)) & 31; }

// ---- packed f32x2 helpers (sm_100a) ----
__device__ __forceinline__ ull pk2(float x, float y) {
    ull r; asm("mov.b64 %0, {%1,%2};" : "=l"(r) : "f"(x), "f"(y)); return r;
}
__device__ __forceinline__ ull pkb(float x) { return pk2(x, x); }
__device__ __forceinline__ void upk(ull v, float& x, float& y) {
    asm("mov.b64 {%0,%1}, %2;" : "=f"(x), "=f"(y) : "l"(v));
}
__device__ __forceinline__ ull fma2(ull a, ull b, ull c) {
    ull d; asm("fma.rn.f32x2 %0, %1, %2, %3;" : "=l"(d) : "l"(a), "l"(b), "l"(c)); return d;
}
__device__ __forceinline__ ull mul2(ull a, ull b) {
    ull d; asm("mul.rn.f32x2 %0, %1, %2;" : "=l"(d) : "l"(a), "l"(b)); return d;
}
__device__ __forceinline__ ull add2(ull a, ull b) {
    ull d; asm("add.rn.f32x2 %0, %1, %2;" : "=l"(d) : "l"(a), "l"(b)); return d;
}
// fp16x2 <-> f32x2 conversion
__device__ __forceinline__ uint32_t pkh(ull v) {
    float x, y; upk(v, x, y);
    __half2 h = __floats2half2_rn(x, y);
    return *reinterpret_cast<uint32_t*>(&h);
}
__device__ __forceinline__ ull uph(uint32_t u) {
    __half2 h = *reinterpret_cast<__half2*>(&u);
    float2 f = __half22float2(h);
    return pk2(f.x, f.y);
}
// packed fp16x2 math
__device__ __forceinline__ uint32_t hfma2u(uint32_t a, uint32_t b, uint32_t c) {
    uint32_t d;
    asm("fma.rn.f16x2 %0, %1, %2, %3;" : "=r"(d) : "r"(a), "r"(b), "r"(c));
    return d;
}
__device__ __forceinline__ uint32_t pkh2f(float x) {
    __half2 h = __float2half2_rn(x);
    return *reinterpret_cast<uint32_t*>(&h);
}

// ---- tensor-core helpers ----
__device__ __forceinline__ void ldsm_x4(uint32_t& r0, uint32_t& r1,
                                        uint32_t& r2, uint32_t& r3, uint32_t addr) {
    asm volatile("ldmatrix.sync.aligned.m8n8.x4.shared.b16 {%0,%1,%2,%3}, [%4];"
                 : "=r"(r0), "=r"(r1), "=r"(r2), "=r"(r3) : "r"(addr));
}
__device__ __forceinline__ void ldsm_x4_t(uint32_t& r0, uint32_t& r1,
                                          uint32_t& r2, uint32_t& r3, uint32_t addr) {
    asm volatile("ldmatrix.sync.aligned.m8n8.x4.trans.shared.b16 {%0,%1,%2,%3}, [%4];"
                 : "=r"(r0), "=r"(r1), "=r"(r2), "=r"(r3) : "r"(addr));
}
__device__ __forceinline__ void mma16816(float* c, const uint32_t* a, const uint32_t* b) {
    asm volatile("mma.sync.aligned.m16n8k16.row.col.f32.f16.f16.f32 "
                 "{%0,%1,%2,%3}, {%4,%5,%6,%7}, {%8,%9}, {%0,%1,%2,%3};"
                 : "+f"(c[0]), "+f"(c[1]), "+f"(c[2]), "+f"(c[3])
                 : "r"(a[0]), "r"(a[1]), "r"(a[2]), "r"(a[3]), "r"(b[0]), "r"(b[1]));
}

// ---------------------------------------------------------------------------
// Kernel 0: fp32 -> fp16 conversion of data and W_graph
// ---------------------------------------------------------------------------
#define NA4 (BATCH * D_IN / 4)
#define NB4 (D_IN * D_H / 4)
__global__ void __launch_bounds__(256)
cvt_kernel(const float* __restrict__ data, const float* __restrict__ Wg)
{
    const int i = blockIdx.x * 256 + threadIdx.x;
    if (i < NA4) {
        float4 v = reinterpret_cast<const float4*>(data)[i];
        __half2 h0 = __floats2half2_rn(v.x, v.y);
        __half2 h1 = __floats2half2_rn(v.z, v.w);
        reinterpret_cast<__half2*>(g_Ah)[i * 2 + 0] = h0;
        reinterpret_cast<__half2*>(g_Ah)[i * 2 + 1] = h1;
    } else {
        const int j = i - NA4;
        if (j < NB4) {
            float4 v = reinterpret_cast<const float4*>(Wg)[j];
            __half2 h0 = __floats2half2_rn(v.x, v.y);
            __half2 h1 = __floats2half2_rn(v.z, v.w);
            reinterpret_cast<__half2*>(g_Bh)[j * 2 + 0] = h0;
            reinterpret_cast<__half2*>(g_Bh)[j * 2 + 1] = h1;
        }
    }
}

// ---------------------------------------------------------------------------
// Kernel 1: h = relu(A_fp16 @ B_fp16 + bias), fp32 accum, HMMA 16816.
// fp16-input version; epilogue stores h as fp16.
// ---------------------------------------------------------------------------
__global__ void __launch_bounds__(256)
hgemm_relu_kernel(const float* __restrict__ bias)
{
    __shared__ __half As[128][40];
    __shared__ __half Bs[32][136];

    const int tid  = threadIdx.x;
    const int wid  = tid >> 5;
    const int lane = tid & 31;
    const int rowBase = blockIdx.y * 128;
    const int colBase = blockIdx.x * 128;
    const int wm = (wid >> 2) * 64;
    const int wn = (wid & 3) * 32;

    float acc[4][4][4];
#pragma unroll
    for (int mb = 0; mb < 4; mb++)
#pragma unroll
        for (int nb = 0; nb < 4; nb++)
#pragma unroll
            for (int k = 0; k < 4; k++) acc[mb][nb][k] = 0.f;

    const int aIdx0 = tid * 2;
    const int aRow0 = aIdx0 >> 2, aChk0 = (aIdx0 & 3);
    const int aRow1 = (aIdx0 + 1) >> 2, aChk1 = ((aIdx0 + 1) & 3);
    const int bRow0 = aIdx0 >> 4, bChk0 = (aIdx0 & 15);
    const int bRow1 = (aIdx0 + 1) >> 4, bChk1 = ((aIdx0 + 1) & 15);

    const __half* Ag = g_Ah + (size_t)(rowBase)*D_IN;
    const __half* Bg = g_Bh;

    const int g = lane >> 3, li = lane & 7;
    const uint32_t AsBase = (uint32_t)__cvta_generic_to_shared(&As[0][0]);
    const uint32_t BsBase = (uint32_t)__cvta_generic_to_shared(&Bs[0][0]);
    const uint32_t addrA0 = AsBase + (uint32_t)((wm + (g & 1) * 8 + li) * 80 + (g >> 1) * 16);
    const uint32_t addrB0 = BsBase + (uint32_t)(((g & 1) * 8 + li) * 272 + (wn + (g >> 1) * 8) * 2);

    int4 pa0, pa1, pb0, pb1;
    {
        const int4* Ap = reinterpret_cast<const int4*>(Ag);
        pa0 = Ap[aRow0 * 32 + aChk0];
        pa1 = Ap[aRow1 * 32 + aChk1];
        pb0 = *reinterpret_cast<const int4*>(Bg + (size_t)bRow0 * D_H + colBase + bChk0 * 8);
        pb1 = *reinterpret_cast<const int4*>(Bg + (size_t)bRow1 * D_H + colBase + bChk1 * 8);
    }

    for (int kc = 0; kc < 8; kc++) {
        *reinterpret_cast<int4*>(&As[aRow0][aChk0 * 8]) = pa0;
        *reinterpret_cast<int4*>(&As[aRow1][aChk1 * 8]) = pa1;
        *reinterpret_cast<int4*>(&Bs[bRow0][bChk0 * 8]) = pb0;
        *reinterpret_cast<int4*>(&Bs[bRow1][bChk1 * 8]) = pb1;
        __syncthreads();

        if (kc < 7) {
            const int k0n = (kc + 1) * 32;
            pa0 = *reinterpret_cast<const int4*>(Ag + (size_t)aRow0 * D_IN + k0n + aChk0 * 8);
            pa1 = *reinterpret_cast<const int4*>(Ag + (size_t)aRow1 * D_IN + k0n + aChk1 * 8);
            pb0 = *reinterpret_cast<const int4*>(Bg + (size_t)(k0n + bRow0) * D_H + colBase + bChk0 * 8);
            pb1 = *reinterpret_cast<const int4*>(Bg + (size_t)(k0n + bRow1) * D_H + colBase + bChk1 * 8);
        }

#pragma unroll
        for (int k16 = 0; k16 < 2; k16++) {
            uint32_t a[4][4];
#pragma unroll
            for (int mb = 0; mb < 4; mb++)
                ldsm_x4(a[mb][0], a[mb][1], a[mb][2], a[mb][3],
                        addrA0 + (uint32_t)(mb * 16 * 80 + k16 * 32));
            uint32_t b[4][2];
#pragma unroll
            for (int nb2 = 0; nb2 < 2; nb2++) {
                uint32_t r0, r1, r2, r3;
                ldsm_x4_t(r0, r1, r2, r3,
                          addrB0 + (uint32_t)(nb2 * 32 + k16 * 16 * 272));
                b[nb2 * 2 + 0][0] = r0; b[nb2 * 2 + 0][1] = r1;
                b[nb2 * 2 + 1][0] = r2; b[nb2 * 2 + 1][1] = r3;
            }
#pragma unroll
            for (int mb = 0; mb < 4; mb++)
#pragma unroll
                for (int nb = 0; nb < 4; nb++)
                    mma16816(acc[mb][nb], a[mb], b[nb]);
        }
        __syncthreads();
    }

    // epilogue: bias + relu + fp16 store
#pragma unroll
    for (int nb = 0; nb < 4; nb++) {
        const int col = colBase + wn + nb * 8 + (lane & 3) * 2;
        const float2 bz = *reinterpret_cast<const float2*>(&bias[col]);
#pragma unroll
        for (int mb = 0; mb < 4; mb++) {
            const int row0 = rowBase + wm + mb * 16 + (lane >> 2);
            __half2 h0 = __floats2half2_rn(fmaxf(acc[mb][nb][0] + bz.x, 0.f),
                                           fmaxf(acc[mb][nb][1] + bz.y, 0.f));
            __half2 h1 = __floats2half2_rn(fmaxf(acc[mb][nb][2] + bz.x, 0.f),
                                           fmaxf(acc[mb][nb][3] + bz.y, 0.f));
            *reinterpret_cast<__half2*>(&g_h16[(size_t)row0 * D_H + col]) = h0;
            *reinterpret_cast<__half2*>(&g_h16[(size_t)(row0 + 8) * D_H + col]) = h1;
        }
    }
}

// ---------------------------------------------------------------------------
// Kernel 1.5: pre_kernel — x = h @ W_pre + b_pre -> angles -> g_cs.
// h read as fp16 pairs (halved DRAM traffic).
// ---------------------------------------------------------------------------
__global__ void __launch_bounds__(256)
pre_kernel(const float* __restrict__ Wp,   // [D_H, NQ] row-major
           const float* __restrict__ bp,   // [NQ]
           const float* __restrict__ qw)   // [NLAYERS*NQ]
{
    __shared__ float WpS[NQ][D_H];         // 24 KB transposed copy

    const int tid  = threadIdx.x;
    const int wid  = tid >> 5;
    const int lane = tid & 31;

    for (int e = tid; e < NQ * D_H; e += 256) {
        const int q = e >> 9;
        const int k = e & 511;
        WpS[q][k] = Wp[k * NQ + q];
    }
    __syncthreads();

    const int s = blockIdx.x * 8 + wid;
    const __half* hr = g_h16 + (size_t)s * D_H;

    ull xa2[NQ];
#pragma unroll
    for (int q = 0; q < NQ; q++) xa2[q] = 0ull;

#pragma unroll
    for (int j = 0; j < 8; j++) {
        const int k0 = j * 64 + lane * 2;
        const uint32_t hraw = *reinterpret_cast<const uint32_t*>(hr + k0);
        const ull hv2 = uph(hraw);         // 2 fp16 -> f32x2
#pragma unroll
        for (int q = 0; q < NQ; q++) {
            const ull wq2 = *reinterpret_cast<const ull*>(&WpS[q][k0]);
            xa2[q] = fma2(hv2, wq2, xa2[q]);
        }
    }

    float myx = 0.f;
#pragma unroll
    for (int q = 0; q < NQ; q++) {
        float a, b;
        upk(xa2[q], a, b);
        float v = a + b;
#pragma unroll
        for (int o = 16; o; o >>= 1) v += __shfl_xor_sync(FULLM, v, o);
        if (lane == q) myx = v;
    }

    if (lane < NQ) {
        const float x = myx + bp[lane];
        const float half = fmaf(0.5f, atanf(x), 0.78539816339744831f)
                         + 0.5f * qw[lane];
        float sv, cv;
        sincosf(half, &sv, &cv);
        g_cs[(size_t)s * NQ + lane] = make_float2(cv, sv);
    }
}

// ---------------------------------------------------------------------------
// Kernel 2: 12-qubit sim -> expectation. 2 samples per block.
// All-fp16 layer loop; launch_bounds(128,8).
// ---------------------------------------------------------------------------
__global__ void __launch_bounds__(128, 8)
sim_kernel(const float* __restrict__ qw,   // [NLAYERS*NQ]
           float* __restrict__ out)        // [BATCH]
{
    extern __shared__ uint32_t SH[];       // 4096 fp16x2 amplitudes (16 KB)
    __shared__ uint32_t qh[NLAYERS * NQ];  // {t, t}  packed fp16x2
    __shared__ uint32_t qhn[NLAYERS * NQ]; // {-t,-t} packed fp16x2
    __shared__ float cS[2][NQ], sS[2][NQ];
    __shared__ float2 redc[4];
    __shared__ float CfS;

    const int tid  = threadIdx.x;
    const int w    = tid >> 5;      // 0..3
    const int lane = tid & 31;
    const int s0   = blockIdx.x * 2;

    if (tid < NLAYERS * NQ) {
        float a = qw[tid] * 0.5f;
        float sv, cv;
        sincosf(a, &sv, &cv);
        const float t = sv / cv;
        qh[tid]  = pkh2f(t);
        qhn[tid] = pkh2f(-t);
    }
    if (tid == 64) {
        float C = 1.f;
        for (int i = NQ; i < NLAYERS * NQ; i++) C *= cosf(qw[i] * 0.5f);
        CfS = C;
    }
    if (tid >= 96 && tid < 96 + 2 * NQ) {
        const int e = tid - 96;
        const int smp = e / NQ, q = e % NQ;
        const float2 v = g_cs[(size_t)(s0 + smp) * NQ + q];
        cS[smp][q] = v.x;
        sS[smp][q] = v.y;
    }
    __syncthreads();

    // ---- initial product state, layout A, fp32 (merged layer-1 RYs) ----
    float bx = CfS, by = CfS;
#pragma unroll
    for (int b = 0; b < 5; b++) {
        const int wr = 11 - b;
        if ((lane >> b) & 1) { bx *= sS[0][wr]; by *= sS[1][wr]; }
        else                 { bx *= cS[0][wr]; by *= cS[1][wr]; }
    }
    if (w & 1)  { bx *= sS[0][6]; by *= sS[1][6]; }
    else        { bx *= cS[0][6]; by *= cS[1][6]; }
    if (w >> 1) { bx *= sS[0][5]; by *= sS[1][5]; }
    else        { bx *= cS[0][5]; by *= cS[1][5]; }

    ull st[32];
    st[0] = pk2(bx, by);
#pragma unroll
    for (int tb = 0; tb < 5; tb++) {
        const int wirew = 4 - tb;
        const ull cp = pk2(cS[0][wirew], cS[1][wirew]);
        const ull sp = pk2(sS[0][wirew], sS[1][wirew]);
#pragma unroll
        for (int r = 0; r < (1 << tb); r++) {
            st[r | (1 << tb)] = mul2(st[r], sp);
            st[r] = mul2(st[r], cp);
        }
    }

    // one-time pack to fp16x2
    uint32_t sh[32];
#pragma unroll
    for (int r = 0; r < 32; r++) sh[r] = pkh(st[r]);

    // ---- storage-map bases:  sigma(q) = q ^ e5(q[9:5]) ----
    const int e5w = e5(w);
    const int base2 = (w << 10) | (lane << 5);
    const int e5l = e5(lane);
    int RB1;
    {
        const int g0 = base2 ^ (base2 >> 1);
        RB1 = g0 ^ e5((g0 >> 5) & 31);
    }
    const int tAlo = (w << 5) | (lane ^ e5w);

    // ---- 3 remaining layers, all-fp16 pipeline ----
#pragma unroll 1
    for (int ell = 0; ell < 3; ell++) {
        const int qb = NQ * (ell + 1);

        // trip: A -> B composed with gray perm
        __syncthreads();
#pragma unroll
        for (int r = 0; r < 32; r++)
            SH[(r << 7) | (tAlo ^ e5((r & 7) << 2))] = sh[r];
        __syncthreads();
#pragma unroll
        for (int r = 0; r < 32; r++)
            sh[r] = SH[RB1 ^ gray5(r)];

        // wires 7..11 on layout-B reg bits (bt = 11-u), fp16x2
#pragma unroll
        for (int u = 7; u < 12; u++) {
            const uint32_t tp = qh[qb + u];
            const uint32_t np = qhn[qb + u];
            const int bt = 11 - u;
#pragma unroll
            for (int r = 0; r < 32; r++) {
                if (((r >> bt) & 1) == 0) {
                    const int j = r | (1 << bt);
                    const uint32_t A = sh[r], B = sh[j];
                    sh[r] = hfma2u(np, B, A);
                    sh[j] = hfma2u(tp, A, B);
                }
            }
        }

        // wire 6 (lane bit 0) and wire 5 (lane bit 1): 32-bit shfl + hfma2
        {
            const uint32_t sg6 = (lane & 1) ? qh[qb + 6] : qhn[qb + 6];
#pragma unroll
            for (int r = 0; r < 32; r++) {
                const uint32_t p = __shfl_xor_sync(FULLM, sh[r], 1);
                sh[r] = hfma2u(sg6, p, sh[r]);
            }
            const uint32_t sg5 = ((lane >> 1) & 1) ? qh[qb + 5] : qhn[qb + 5];
#pragma unroll
            for (int r = 0; r < 32; r++) {
                const uint32_t p = __shfl_xor_sync(FULLM, sh[r], 2);
                sh[r] = hfma2u(sg5, p, sh[r]);
            }
        }

        // trip: B -> A
        __syncthreads();
#pragma unroll
        for (int r = 0; r < 32; r++)
            SH[base2 | (r ^ e5l)] = sh[r];
        __syncthreads();
#pragma unroll
        for (int r = 0; r < 32; r++)
            sh[r] = SH[(r << 7) | (tAlo ^ e5((r & 7) << 2))];

        // wires 0..4 on layout-A reg bits (bt = 4-u), fp16x2
#pragma unroll
        for (int u = 0; u < 5; u++) {
            const uint32_t tp = qh[qb + u];
            const uint32_t np = qhn[qb + u];
            const int bt = 4 - u;
#pragma unroll
            for (int r = 0; r < 32; r++) {
                if (((r >> bt) & 1) == 0) {
                    const int j = r | (1 << bt);
                    const uint32_t A = sh[r], B = sh[j];
                    sh[r] = hfma2u(np, B, A);
                    sh[j] = hfma2u(tp, A, B);
                }
            }
        }
    }

    // ---- measurement (fp32) with final gray perm folded into weights ----
    int ex = tid;
    ex ^= ex >> 1; ex ^= ex >> 2; ex ^= ex >> 4;
    const int Pt = __popc(ex & 127);

    ull acc1 = 0ull, accP = 0ull, accM = 0ull;
#pragma unroll
    for (int r = 0; r < 32; r++) {
        const int a = cpop(e5(r));
        const int p = cpop(r) & 1;
        const float Ar = p ? (float)(-2 - 2 * a) : (float)(12 - 2 * a);
        const ull v = uph(sh[r]);
        const ull t = mul2(v, v);
        acc1 = fma2(pkb(Ar), t, acc1);
        if (p) accP = add2(accP, t);
        else   accM = add2(accM, t);
    }
    const ull S = fma2(pkb(-1.f), accM, accP);
    const ull res = fma2(pkb(2.f * (float)Pt), S, acc1);

    float rx, ry;
    upk(res, rx, ry);
#pragma unroll
    for (int o = 16; o; o >>= 1) {
        rx += __shfl_xor_sync(FULLM, rx, o);
        ry += __shfl_xor_sync(FULLM, ry, o);
    }
    if (lane == 0) redc[w] = make_float2(rx, ry);
    __syncthreads();
    if (tid == 0) {
        out[s0]     = redc[0].x + redc[1].x + redc[2].x + redc[3].x;
        out[s0 + 1] = redc[0].y + redc[1].y + redc[2].y + redc[3].y;
    }
}

// ---------------------------------------------------------------------------
extern "C" void kernel_launch(void* const* d_in, const int* in_sizes, int n_in,
                              void* d_out, int out_size)
{
    const float* data = (const float*)d_in[0];
    const float* Wg   = (const float*)d_in[1];
    const float* bg   = (const float*)d_in[2];
    const float* Wp   = (const float*)d_in[3];
    const float* bp   = (const float*)d_in[4];
    const float* qw   = (const float*)d_in[5];
    float* out = (float*)d_out;

    cvt_kernel<<<(NA4 + NB4 + 255) / 256, 256>>>(data, Wg);

    dim3 gGrid(D_H / 128, BATCH / 128);
    hgemm_relu_kernel<<<gGrid, 256>>>(bg);

    pre_kernel<<<BATCH / 8, 256>>>(Wp, bp, qw);

    sim_kernel<<<BATCH / 2, 128, 16384>>>(qw, out);
}